// round 1
// baseline (speedup 1.0000x reference)
#include <cuda_runtime.h>
#include <cuda_bf16.h>

__global__ __launch_bounds__(256)
void gaussian_cov_kernel(const float* __restrict__ scaling,
                         const float4* __restrict__ rot,
                         float2* __restrict__ out,
                         int n)
{
    int i = blockIdx.x * blockDim.x + threadIdx.x;
    if (i >= n) return;

    // s^2 = exp(2 * raw)  (cov only ever uses s squared)
    float s0 = __expf(2.0f * scaling[3 * i + 0]);
    float s1 = __expf(2.0f * scaling[3 * i + 1]);
    float s2 = __expf(2.0f * scaling[3 * i + 2]);

    float4 q = rot[i];
    float inv = rsqrtf(q.x * q.x + q.y * q.y + q.z * q.z + q.w * q.w);
    float w = q.x * inv;
    float x = q.y * inv;
    float y = q.z * inv;
    float z = q.w * inv;

    // Rotation matrix rows
    float r00 = 1.0f - 2.0f * (y * y + z * z);
    float r01 = 2.0f * (x * y - w * z);
    float r02 = 2.0f * (x * z + w * y);
    float r10 = 2.0f * (x * y + w * z);
    float r11 = 1.0f - 2.0f * (x * x + z * z);
    float r12 = 2.0f * (y * z - w * x);
    float r20 = 2.0f * (x * z - w * y);
    float r21 = 2.0f * (y * z + w * x);
    float r22 = 1.0f - 2.0f * (x * x + y * y);

    // cov[i][k] = sum_j R[i][j] * R[k][j] * s[j]^2
    float c00 = r00 * r00 * s0 + r01 * r01 * s1 + r02 * r02 * s2;
    float c01 = r00 * r10 * s0 + r01 * r11 * s1 + r02 * r12 * s2;
    float c02 = r00 * r20 * s0 + r01 * r21 * s1 + r02 * r22 * s2;
    float c11 = r10 * r10 * s0 + r11 * r11 * s1 + r12 * r12 * s2;
    float c12 = r10 * r20 * s0 + r11 * r21 * s1 + r12 * r22 * s2;
    float c22 = r20 * r20 * s0 + r21 * r21 * s1 + r22 * r22 * s2;

    // 6 floats per row, 24B stride -> 8B aligned float2 stores
    out[3 * i + 0] = make_float2(c00, c01);
    out[3 * i + 1] = make_float2(c02, c11);
    out[3 * i + 2] = make_float2(c12, c22);
}

extern "C" void kernel_launch(void* const* d_in, const int* in_sizes, int n_in,
                              void* d_out, int out_size)
{
    const float*  scaling = (const float*)d_in[0];   // [N,3] float32
    const float4* rot     = (const float4*)d_in[1];  // [N,4] float32, 16B rows
    float2*       out     = (float2*)d_out;          // [N,6] float32

    int n = in_sizes[0] / 3;  // N
    int threads = 256;
    int blocks = (n + threads - 1) / threads;
    gaussian_cov_kernel<<<blocks, threads>>>(scaling, rot, out, n);
}